// round 1
// baseline (speedup 1.0000x reference)
#include <cuda_runtime.h>
#include <math.h>

// Problem constants
#define BB   256          // batch
#define NN   128          // seq len
#define DM   256          // model dim
#define NHH  4            // heads
#define HDD  64           // head dim
#define MR   (BB*NN)      // 32768 total rows

// ---------------------------------------------------------------------------
// Scratch (static __device__ arrays; allocation-free per harness rules)
// ---------------------------------------------------------------------------
__device__ float g_q[MR*DM];
__device__ float g_k[MR*DM];
__device__ float g_v[MR*DM];
__device__ float g_attn[MR*DM];
__device__ float g_head[MR*DM];
__device__ float g_childavg[MR*DM];
__device__ float g_childmsg[MR*DM];
__device__ float g_sib[MR*DM];
__device__ float g_gate[MR*DM];
__device__ float g_tr[MR*DM];
__device__ float g_cnt[MR];
__device__ float g_bh[MR];
__device__ float g_bd[MR];

__device__ __forceinline__ float gelu_f(float x) {
    return 0.5f * x * (1.0f + erff(x * 0.7071067811865475f));
}
__device__ __forceinline__ float sigmoid_f(float x) {
    return 1.0f / (1.0f + expf(-x));
}

// ---------------------------------------------------------------------------
// GEMM: C[MR,256] = act( concat(A0..A_{NSRC-1})[MR, NSRC*256] @ W + bias )
// Tiles: BM=128, BN=128, BK=16; 256 threads, 8x8 microtile (split 4+4 halves).
// ACT: 0=none, 1=gelu, 2=sigmoid
// ---------------------------------------------------------------------------
template<int NSRC, int ACT>
__global__ void __launch_bounds__(256) gemm_k(
    const float* __restrict__ A0, const float* __restrict__ A1,
    const float* __restrict__ A2, const float* __restrict__ A3,
    const float* __restrict__ W, const float* __restrict__ bias,
    float* __restrict__ C)
{
    constexpr int K = NSRC * 256;
    __shared__ float As[16][132];
    __shared__ float Ws[16][128];

    const int tid = threadIdx.x;
    const int m0 = blockIdx.x * 128;
    const int n0 = blockIdx.y * 128;
    const int tr = tid >> 4;            // 0..15 (row group)
    const int tc = tid & 15;            // 0..15 (col group)
    // A tile load: thread -> rows ra, ra+64 ; 4 cols at ca
    const int ra = tid >> 2;            // 0..63
    const int ca = (tid & 3) << 2;      // 0,4,8,12
    // W tile load: thread -> row rwl, two float4 at cwl and cwl+64
    const int rwl = tid >> 4;           // 0..15
    const int cwl = (tid & 15) << 2;    // 0..60

    float acc[8][8];
    #pragma unroll
    for (int i = 0; i < 8; i++)
        #pragma unroll
        for (int j = 0; j < 8; j++) acc[i][j] = 0.f;

    for (int kt = 0; kt < K; kt += 16) {
        const float* A = A0;
        if (NSRC > 1) {
            int s = kt >> 8;
            if (s == 1) A = A1;
            else if (NSRC > 2 && s == 2) A = A2;
            else if (NSRC > 3 && s == 3) A = A3;
        }
        const int kk0 = kt & 255;
        float4 a0 = *(const float4*)(A + (size_t)(m0 + ra) * 256 + kk0 + ca);
        float4 a1 = *(const float4*)(A + (size_t)(m0 + ra + 64) * 256 + kk0 + ca);
        float4 w0 = *(const float4*)(W + (size_t)(kt + rwl) * 256 + n0 + cwl);
        float4 w1 = *(const float4*)(W + (size_t)(kt + rwl) * 256 + n0 + cwl + 64);
        __syncthreads();
        As[ca + 0][ra] = a0.x; As[ca + 1][ra] = a0.y;
        As[ca + 2][ra] = a0.z; As[ca + 3][ra] = a0.w;
        As[ca + 0][ra + 64] = a1.x; As[ca + 1][ra + 64] = a1.y;
        As[ca + 2][ra + 64] = a1.z; As[ca + 3][ra + 64] = a1.w;
        *(float4*)&Ws[rwl][cwl]      = w0;
        *(float4*)&Ws[rwl][cwl + 64] = w1;
        __syncthreads();
        #pragma unroll
        for (int kk = 0; kk < 16; kk++) {
            float4 av0 = *(const float4*)&As[kk][tr << 2];
            float4 av1 = *(const float4*)&As[kk][64 + (tr << 2)];
            float4 bv0 = *(const float4*)&Ws[kk][tc << 2];
            float4 bv1 = *(const float4*)&Ws[kk][64 + (tc << 2)];
            float a_[8] = {av0.x, av0.y, av0.z, av0.w, av1.x, av1.y, av1.z, av1.w};
            float b_[8] = {bv0.x, bv0.y, bv0.z, bv0.w, bv1.x, bv1.y, bv1.z, bv1.w};
            #pragma unroll
            for (int i = 0; i < 8; i++)
                #pragma unroll
                for (int j = 0; j < 8; j++)
                    acc[i][j] += a_[i] * b_[j];
        }
    }

    float bvv[8];
    #pragma unroll
    for (int j = 0; j < 8; j++) {
        int c = (j < 4) ? ((tc << 2) + j) : (64 + (tc << 2) + j - 4);
        bvv[j] = bias ? bias[n0 + c] : 0.f;
    }
    #pragma unroll
    for (int i = 0; i < 8; i++) {
        int r = (i < 4) ? ((tr << 2) + i) : (64 + (tr << 2) + i - 4);
        int row = m0 + r;
        float o[8];
        #pragma unroll
        for (int j = 0; j < 8; j++) {
            float v = acc[i][j] + bvv[j];
            if (ACT == 1) v = gelu_f(v);
            else if (ACT == 2) v = sigmoid_f(v);
            o[j] = v;
        }
        float4 s0 = {o[0], o[1], o[2], o[3]};
        float4 s1 = {o[4], o[5], o[6], o[7]};
        *(float4*)(C + (size_t)row * 256 + n0 + (tc << 2))      = s0;
        *(float4*)(C + (size_t)row * 256 + n0 + 64 + (tc << 2)) = s1;
    }
}

// ---------------------------------------------------------------------------
// Attention per (b, h). MODE 0: keys/values row-gathered via pred_heads
// (head attention, no mask). MODE 1: sibling self-attention with block mask.
// 128 threads = one per query row. Dynamic shared: K, V, scores, ph, mask.
// ---------------------------------------------------------------------------
#define ATTN_SMEM ((8192 + 8192 + 128*129 + 128 + 128) * 4)

template<int MODE>
__global__ void __launch_bounds__(128) attn_k(
    const float* __restrict__ Q, const float* __restrict__ Kp,
    const float* __restrict__ Vp, const int* __restrict__ ph,
    const float* __restrict__ mask, float* __restrict__ O)
{
    extern __shared__ float sm[];
    float* Ks  = sm;                      // [128][64]
    float* Vs  = sm + 8192;               // [128][64]
    float* S   = sm + 16384;              // [128][129]
    int*   phs = (int*)(sm + 16384 + 16512);
    float* msk = sm + 16384 + 16512 + 128;

    const int b = blockIdx.x, h = blockIdx.y;
    const int t = threadIdx.x;
    const int rowbase = b * NN;

    phs[t] = ph[rowbase + t];
    msk[t] = mask[rowbase + t];
    __syncthreads();

    for (int i = t; i < 2048; i += 128) {        // 128 rows x 16 float4
        int krow = i >> 4;
        int f4   = (i & 15) << 2;
        int src  = (MODE == 0) ? min(max(phs[krow], 0), NN - 1) : krow;
        size_t off = (size_t)(rowbase + src) * DM + h * HDD + f4;
        *(float4*)&Ks[krow * 64 + f4] = *(const float4*)(Kp + off);
        *(float4*)&Vs[krow * 64 + f4] = *(const float4*)(Vp + off);
    }
    __syncthreads();

    float q[64];
    {
        size_t off = (size_t)(rowbase + t) * DM + h * HDD;
        #pragma unroll
        for (int d = 0; d < 64; d += 4) {
            float4 v = *(const float4*)(Q + off + d);
            q[d] = v.x; q[d+1] = v.y; q[d+2] = v.z; q[d+3] = v.w;
        }
    }
    float* Srow = S + t * 129;
    const int myph = phs[t];
    const float mym = msk[t];
    for (int k = 0; k < 128; k++) {
        float s = 0.f;
        #pragma unroll
        for (int d = 0; d < 64; d += 4) {
            float4 kv = *(const float4*)&Ks[k * 64 + d];
            s += q[d]*kv.x + q[d+1]*kv.y + q[d+2]*kv.z + q[d+3]*kv.w;
        }
        s *= 0.125f;  // 1/sqrt(64)
        if (MODE == 1) {
            bool sib = (phs[k] == myph) && (k != t) && (msk[k] > 0.f) && (mym > 0.f);
            if (!sib) s = -1e9f;
        }
        Srow[k] = s;
    }
    float mx = -3.4e38f;
    for (int k = 0; k < 128; k++) mx = fmaxf(mx, Srow[k]);
    float l = 0.f;
    for (int k = 0; k < 128; k++) { float e = expf(Srow[k] - mx); Srow[k] = e; l += e; }
    float inv = 1.f / l;

    float o[64];
    #pragma unroll
    for (int d = 0; d < 64; d++) o[d] = 0.f;
    for (int k = 0; k < 128; k++) {
        float p = Srow[k];
        #pragma unroll
        for (int d = 0; d < 64; d += 4) {
            float4 vv = *(const float4*)&Vs[k * 64 + d];
            o[d] += p*vv.x; o[d+1] += p*vv.y; o[d+2] += p*vv.z; o[d+3] += p*vv.w;
        }
    }
    {
        size_t off = (size_t)(rowbase + t) * DM + h * HDD;
        #pragma unroll
        for (int d = 0; d < 64; d += 4) {
            float4 v = {o[d]*inv, o[d+1]*inv, o[d+2]*inv, o[d+3]*inv};
            *(float4*)(O + off + d) = v;
        }
    }
}

// ---------------------------------------------------------------------------
// Child scatter-mean
// ---------------------------------------------------------------------------
__global__ void zero_child_k() {
    int i = blockIdx.x * 256 + threadIdx.x;
    g_childavg[i] = 0.f;
    if (i < MR) g_cnt[i] = 0.f;
}
__global__ void scatter_sum_k(const float* __restrict__ Hr, const int* __restrict__ ph) {
    int idx = blockIdx.x * 256 + threadIdx.x;   // over MR*DM
    int row = idx >> 8;
    int d   = idx & 255;
    int b   = row >> 7;
    int hh  = min(max(ph[row], 0), NN - 1);
    atomicAdd(&g_childavg[(size_t)(((b << 7) | hh) << 8) + d], Hr[idx]);
}
__global__ void scatter_cnt_k(const int* __restrict__ ph, const float* __restrict__ mask) {
    int row = blockIdx.x * 256 + threadIdx.x;   // over MR
    int b   = row >> 7;
    int hh  = min(max(ph[row], 0), NN - 1);
    atomicAdd(&g_cnt[(b << 7) | hh], mask[row]);
}
__global__ void avg_k() {
    int idx = blockIdx.x * 256 + threadIdx.x;   // over MR*DM
    g_childavg[idx] /= fmaxf(g_cnt[idx >> 8], 1.f);
}

// ---------------------------------------------------------------------------
// Fused gate*update + residual + LayerNorm (one block per row, 256 threads)
// ---------------------------------------------------------------------------
__global__ void __launch_bounds__(256) fuse_ln_k(
    float* __restrict__ Hr, const float* __restrict__ g, const float* __restrict__ u,
    const float* __restrict__ lg, const float* __restrict__ lb)
{
    __shared__ float shs[8], shq[8];
    __shared__ float stat[2];
    int row = blockIdx.x, t = threadIdx.x;
    size_t off = (size_t)row * 256 + t;
    float x = Hr[off] + g[off] * u[off];
    float s = x, qq = x * x;
    #pragma unroll
    for (int o = 16; o; o >>= 1) {
        s  += __shfl_xor_sync(0xffffffffu, s, o);
        qq += __shfl_xor_sync(0xffffffffu, qq, o);
    }
    if ((t & 31) == 0) { shs[t >> 5] = s; shq[t >> 5] = qq; }
    __syncthreads();
    if (t == 0) {
        float S = 0.f, Q = 0.f;
        #pragma unroll
        for (int i = 0; i < 8; i++) { S += shs[i]; Q += shq[i]; }
        float mu = S * (1.f / 256.f);
        float var = fmaxf(Q * (1.f / 256.f) - mu * mu, 0.f);
        stat[0] = mu;
        stat[1] = rsqrtf(var + 1e-5f);
    }
    __syncthreads();
    Hr[off] = (x - stat[0]) * stat[1] * lg[t] + lb[t];
}

// ---------------------------------------------------------------------------
// bias vector: out[row] = dot(X[row,:], w) + b0   (warp per row)
// ---------------------------------------------------------------------------
__global__ void __launch_bounds__(256) biasvec_k(
    const float* __restrict__ X, const float* __restrict__ w,
    const float* __restrict__ b0, float* __restrict__ out)
{
    int row  = blockIdx.x * 8 + (threadIdx.x >> 5);
    int lane = threadIdx.x & 31;
    const float* x = X + (size_t)row * 256;
    float s = 0.f;
    for (int d = lane; d < 256; d += 32) s += x[d] * w[d];
    #pragma unroll
    for (int o = 16; o; o >>= 1) s += __shfl_xor_sync(0xffffffffu, s, o);
    if (lane == 0) out[row] = s + b0[0];
}

// ---------------------------------------------------------------------------
// Final scores: S[b,n,m] = T[b,n,:] . Hd[b,m,:] + bd[b,n] + bh[b,m]
// 64x64 tiles per block, 256 threads, 4x4 microtile
// ---------------------------------------------------------------------------
__global__ void __launch_bounds__(256) scores_k(
    const float* __restrict__ T, const float* __restrict__ Hd,
    const float* __restrict__ bh, const float* __restrict__ bd,
    float* __restrict__ S)
{
    __shared__ float As[16][68];
    __shared__ float Bs[16][68];
    const int b  = blockIdx.x;
    const int n0 = blockIdx.y * 64;
    const int m0 = blockIdx.z * 64;
    const int tid = threadIdx.x;
    const int ar = tid >> 2, ac = (tid & 3) << 2;
    const int ty = tid >> 4, tx = tid & 15;
    const float* Ab = T  + (size_t)b * NN * DM;
    const float* Bbp = Hd + (size_t)b * NN * DM;
    float acc[4][4];
    #pragma unroll
    for (int i = 0; i < 4; i++)
        #pragma unroll
        for (int j = 0; j < 4; j++) acc[i][j] = 0.f;

    for (int kt = 0; kt < 256; kt += 16) {
        float4 a = *(const float4*)(Ab  + (size_t)(n0 + ar) * 256 + kt + ac);
        float4 c = *(const float4*)(Bbp + (size_t)(m0 + ar) * 256 + kt + ac);
        __syncthreads();
        As[ac+0][ar] = a.x; As[ac+1][ar] = a.y; As[ac+2][ar] = a.z; As[ac+3][ar] = a.w;
        Bs[ac+0][ar] = c.x; Bs[ac+1][ar] = c.y; Bs[ac+2][ar] = c.z; Bs[ac+3][ar] = c.w;
        __syncthreads();
        #pragma unroll
        for (int kk = 0; kk < 16; kk++) {
            float4 a4 = *(const float4*)&As[kk][ty << 2];
            float4 b4 = *(const float4*)&Bs[kk][tx << 2];
            float aa[4] = {a4.x, a4.y, a4.z, a4.w};
            float bb[4] = {b4.x, b4.y, b4.z, b4.w};
            #pragma unroll
            for (int i = 0; i < 4; i++)
                #pragma unroll
                for (int j = 0; j < 4; j++)
                    acc[i][j] += aa[i] * bb[j];
        }
    }
    float cb[4];
    #pragma unroll
    for (int j = 0; j < 4; j++) cb[j] = bh[b * NN + m0 + (tx << 2) + j];
    #pragma unroll
    for (int i = 0; i < 4; i++) {
        int n = n0 + (ty << 2) + i;
        float rb = bd[b * NN + n];
        float4 o = {acc[i][0] + rb + cb[0], acc[i][1] + rb + cb[1],
                    acc[i][2] + rb + cb[2], acc[i][3] + rb + cb[3]};
        *(float4*)(S + (size_t)b * NN * NN + (size_t)n * NN + m0 + (tx << 2)) = o;
    }
}

// ---------------------------------------------------------------------------
// Host orchestration
// ---------------------------------------------------------------------------
extern "C" void kernel_launch(void* const* d_in, const int* in_sizes, int n_in,
                              void* d_out, int out_size)
{
    const float* Hin    = (const float*)d_in[0];
    const int*   ph     = (const int*)  d_in[1];
    const float* mask   = (const float*)d_in[2];
    const float* ha_w   = (const float*)d_in[3];
    const float* ha_b   = (const float*)d_in[4];
    const float* sa_w   = (const float*)d_in[5];
    const float* sa_b   = (const float*)d_in[6];
    const float* ct_w   = (const float*)d_in[7];
    const float* ct_b   = (const float*)d_in[8];
    const float* gate_w = (const float*)d_in[9];
    const float* gate_b = (const float*)d_in[10];
    const float* tr_w   = (const float*)d_in[11];
    const float* tr_b   = (const float*)d_in[12];
    const float* ln_g   = (const float*)d_in[13];
    const float* ln_b   = (const float*)d_in[14];
    const float* ahw    = (const float*)d_in[15];
    const float* ahb    = (const float*)d_in[16];
    const float* adw    = (const float*)d_in[17];
    const float* adb    = (const float*)d_in[18];
    const float* bil    = (const float*)d_in[19];
    const float* bhw    = (const float*)d_in[20];
    const float* bhb    = (const float*)d_in[21];
    const float* bdw    = (const float*)d_in[22];
    const float* bdb    = (const float*)d_in[23];

    float* Hr     = (float*)d_out;                 // [B,N,Dm]
    float* scores = Hr + (size_t)MR * DM;          // [B,N,N]

    float *q_, *k_, *v_, *at_, *hm_, *cav_, *cm_, *sb_, *ga_, *tu_, *bhv_, *bdv_;
    cudaGetSymbolAddress((void**)&q_,   g_q);
    cudaGetSymbolAddress((void**)&k_,   g_k);
    cudaGetSymbolAddress((void**)&v_,   g_v);
    cudaGetSymbolAddress((void**)&at_,  g_attn);
    cudaGetSymbolAddress((void**)&hm_,  g_head);
    cudaGetSymbolAddress((void**)&cav_, g_childavg);
    cudaGetSymbolAddress((void**)&cm_,  g_childmsg);
    cudaGetSymbolAddress((void**)&sb_,  g_sib);
    cudaGetSymbolAddress((void**)&ga_,  g_gate);
    cudaGetSymbolAddress((void**)&tu_,  g_tr);
    cudaGetSymbolAddress((void**)&bhv_, g_bh);
    cudaGetSymbolAddress((void**)&bdv_, g_bd);

    cudaFuncSetAttribute(attn_k<0>, cudaFuncAttributeMaxDynamicSharedMemorySize, ATTN_SMEM);
    cudaFuncSetAttribute(attn_k<1>, cudaFuncAttributeMaxDynamicSharedMemorySize, ATTN_SMEM);

    cudaMemcpyAsync(Hr, Hin, sizeof(float) * (size_t)MR * DM, cudaMemcpyDeviceToDevice);

    dim3 gg(MR / 128, 2), gb(256);
    dim3 ag(BB, NHH);
    const int nElem = MR * DM / 256;   // 32768 blocks for elementwise passes

    for (int i = 0; i < 3; i++) {
        const float* hw = ha_w + (size_t)i * 4 * DM * DM;
        const float* hb = ha_b + (size_t)i * 4 * DM;
        // head attention: proj(gather(Hr)) == gather(proj(Hr))
        gemm_k<1,0><<<gg, gb>>>(Hr, 0, 0, 0, hw + 0*65536, hb + 0,   q_);
        gemm_k<1,0><<<gg, gb>>>(Hr, 0, 0, 0, hw + 1*65536, hb + 256, k_);
        gemm_k<1,0><<<gg, gb>>>(Hr, 0, 0, 0, hw + 2*65536, hb + 512, v_);
        attn_k<0><<<ag, 128, ATTN_SMEM>>>(q_, k_, v_, ph, mask, at_);
        gemm_k<1,0><<<gg, gb>>>(at_, 0, 0, 0, hw + 3*65536, hb + 768, hm_);

        // child scatter-mean + gelu MLP on concat(Hr, child_avg)
        zero_child_k   <<<nElem, 256>>>();
        scatter_sum_k  <<<nElem, 256>>>(Hr, ph);
        scatter_cnt_k  <<<MR / 256, 256>>>(ph, mask);
        avg_k          <<<nElem, 256>>>();
        gemm_k<2,1><<<gg, gb>>>(Hr, cav_, 0, 0,
                                ct_w + (size_t)i * 512 * 256, ct_b + i * 256, cm_);

        // sibling masked self-attention
        const float* sw = sa_w + (size_t)i * 4 * DM * DM;
        const float* sbb2 = sa_b + (size_t)i * 4 * DM;
        gemm_k<1,0><<<gg, gb>>>(Hr, 0, 0, 0, sw + 0*65536, sbb2 + 0,   q_);
        gemm_k<1,0><<<gg, gb>>>(Hr, 0, 0, 0, sw + 1*65536, sbb2 + 256, k_);
        gemm_k<1,0><<<gg, gb>>>(Hr, 0, 0, 0, sw + 2*65536, sbb2 + 512, v_);
        attn_k<1><<<ag, 128, ATTN_SMEM>>>(q_, k_, v_, ph, mask, at_);
        gemm_k<1,0><<<gg, gb>>>(at_, 0, 0, 0, sw + 3*65536, sbb2 + 768, sb_);

        // gated fuse + residual + LN
        gemm_k<4,2><<<gg, gb>>>(Hr, hm_, cm_, sb_,
                                gate_w + (size_t)i * 1024 * 256, gate_b + i * 256, ga_);
        gemm_k<4,1><<<gg, gb>>>(Hr, hm_, cm_, sb_,
                                tr_w + (size_t)i * 1024 * 256, tr_b + i * 256, tu_);
        fuse_ln_k<<<MR, 256>>>(Hr, ga_, tu_, ln_g + i * 256, ln_b + i * 256);
    }

    // final biaffine scorer
    gemm_k<1,0><<<gg, gb>>>(Hr, 0, 0, 0, ahw, ahb, q_);        // h_head
    gemm_k<1,0><<<gg, gb>>>(Hr, 0, 0, 0, adw, adb, k_);        // h_dep
    gemm_k<1,0><<<gg, gb>>>(q_, 0, 0, 0, bil, nullptr, v_);    // t = h_head @ bilinear
    biasvec_k<<<MR / 8, 256>>>(q_, bhw, bhb, bhv_);
    biasvec_k<<<MR / 8, 256>>>(k_, bdw, bdb, bdv_);
    scores_k<<<dim3(BB, 2, 2), 256>>>(v_, k_, bhv_, bdv_, scores);
}

// round 2
// speedup vs baseline: 1.2682x; 1.2682x over previous
#include <cuda_runtime.h>
#include <math.h>

// Problem constants
#define BB   256          // batch
#define NN   128          // seq len
#define DM   256          // model dim
#define NHH  4            // heads
#define HDD  64           // head dim
#define MR   (BB*NN)      // 32768 total rows

// ---------------------------------------------------------------------------
// Scratch (static __device__ arrays; allocation-free per harness rules)
// ---------------------------------------------------------------------------
__device__ float g_q[MR*DM];
__device__ float g_k[MR*DM];
__device__ float g_v[MR*DM];
__device__ float g_attn[MR*DM];
__device__ float g_head[MR*DM];
__device__ float g_childavg[MR*DM];
__device__ float g_childmsg[MR*DM];
__device__ float g_sib[MR*DM];
__device__ float g_gate[MR*DM];
__device__ float g_tr[MR*DM];
__device__ float g_bh[MR];
__device__ float g_bd[MR];

__device__ __forceinline__ float gelu_f(float x) {
    return 0.5f * x * (1.0f + erff(x * 0.7071067811865475f));
}
__device__ __forceinline__ float sigmoid_f(float x) {
    return 1.0f / (1.0f + expf(-x));
}
__device__ __forceinline__ void unpk(unsigned long long p, float& x, float& y) {
    asm("mov.b64 {%0, %1}, %2;" : "=f"(x), "=f"(y) : "l"(p));
}

// ---------------------------------------------------------------------------
// GEMM core: C[128x128 tile] = act( concat(A0..A_{NSRC-1}) @ W + bias )
// BM=BN=128, BK=16; 256 threads; 8x8 microtile computed with fma.rn.f32x2
// (packed 2-wide fp32 FMA: 2x the FFMA pipe). Register prefetch double-buffer.
// ---------------------------------------------------------------------------
#define GSM_BYTES ((16*132 + 16*128) * 4)

template<int NSRC>
__device__ __forceinline__ void load_a(
    const float* __restrict__ A0, const float* __restrict__ A1,
    const float* __restrict__ A2, const float* __restrict__ A3,
    int kt, int row, int ca, float4& x0, float4& x1)
{
    const float* A = A0;
    if (NSRC > 1) {
        int s = kt >> 8;
        if (s == 1) A = A1;
        if (NSRC > 2 && s == 2) A = A2;
        if (NSRC > 3 && s == 3) A = A3;
    }
    int kk0 = (kt & 255) + ca;
    x0 = *(const float4*)(A + (size_t)row * 256 + kk0);
    x1 = *(const float4*)(A + (size_t)(row + 64) * 256 + kk0);
}

template<int NSRC, int ACT>
__device__ __forceinline__ void gemm_core(
    const float* __restrict__ A0, const float* __restrict__ A1,
    const float* __restrict__ A2, const float* __restrict__ A3,
    const float* __restrict__ W, const float* __restrict__ bias,
    float* __restrict__ C, int m0, int n0, float* As, float* Ws)
{
    constexpr int K = NSRC * 256;
    const int tid = threadIdx.x;
    const int tr = tid >> 4, tc = tid & 15;
    const int ra = tid >> 2, ca = (tid & 3) << 2;
    const int rwl = tid >> 4, cwl = (tid & 15) << 2;

    unsigned long long acc[8][4];
    #pragma unroll
    for (int i = 0; i < 8; i++)
        #pragma unroll
        for (int j = 0; j < 4; j++) acc[i][j] = 0ull;

    float4 a0, a1, w0, w1;
    load_a<NSRC>(A0, A1, A2, A3, 0, m0 + ra, ca, a0, a1);
    w0 = *(const float4*)(W + (size_t)rwl * 256 + n0 + cwl);
    w1 = *(const float4*)(W + (size_t)rwl * 256 + n0 + cwl + 64);

    for (int kt = 0; kt < K; kt += 16) {
        __syncthreads();
        As[(ca + 0) * 132 + ra] = a0.x; As[(ca + 1) * 132 + ra] = a0.y;
        As[(ca + 2) * 132 + ra] = a0.z; As[(ca + 3) * 132 + ra] = a0.w;
        As[(ca + 0) * 132 + ra + 64] = a1.x; As[(ca + 1) * 132 + ra + 64] = a1.y;
        As[(ca + 2) * 132 + ra + 64] = a1.z; As[(ca + 3) * 132 + ra + 64] = a1.w;
        *(float4*)&Ws[rwl * 128 + cwl]      = w0;
        *(float4*)&Ws[rwl * 128 + cwl + 64] = w1;
        __syncthreads();
        if (kt + 16 < K) {       // prefetch next tile into regs (hides GMEM lat)
            load_a<NSRC>(A0, A1, A2, A3, kt + 16, m0 + ra, ca, a0, a1);
            w0 = *(const float4*)(W + (size_t)(kt + 16 + rwl) * 256 + n0 + cwl);
            w1 = *(const float4*)(W + (size_t)(kt + 16 + rwl) * 256 + n0 + cwl + 64);
        }
        #pragma unroll
        for (int kk = 0; kk < 16; kk++) {
            float4 av0 = *(const float4*)&As[kk * 132 + (tr << 2)];
            float4 av1 = *(const float4*)&As[kk * 132 + 64 + (tr << 2)];
            ulonglong2 bq0 = *(const ulonglong2*)&Ws[kk * 128 + (tc << 2)];
            ulonglong2 bq1 = *(const ulonglong2*)&Ws[kk * 128 + 64 + (tc << 2)];
            float a_[8] = {av0.x, av0.y, av0.z, av0.w, av1.x, av1.y, av1.z, av1.w};
            #pragma unroll
            for (int i = 0; i < 8; i++) {
                unsigned long long ap;
                asm("mov.b64 %0, {%1, %1};" : "=l"(ap) : "f"(a_[i]));
                asm("fma.rn.f32x2 %0, %1, %2, %0;" : "+l"(acc[i][0]) : "l"(ap), "l"(bq0.x));
                asm("fma.rn.f32x2 %0, %1, %2, %0;" : "+l"(acc[i][1]) : "l"(ap), "l"(bq0.y));
                asm("fma.rn.f32x2 %0, %1, %2, %0;" : "+l"(acc[i][2]) : "l"(ap), "l"(bq1.x));
                asm("fma.rn.f32x2 %0, %1, %2, %0;" : "+l"(acc[i][3]) : "l"(ap), "l"(bq1.y));
            }
        }
    }

    float bvv[8];
    #pragma unroll
    for (int j = 0; j < 8; j++) {
        int c = (j < 4) ? ((tc << 2) + j) : (64 + (tc << 2) + j - 4);
        bvv[j] = bias ? bias[n0 + c] : 0.f;
    }
    #pragma unroll
    for (int i = 0; i < 8; i++) {
        int r = (i < 4) ? ((tr << 2) + i) : (64 + (tr << 2) + i - 4);
        float o[8];
        unpk(acc[i][0], o[0], o[1]); unpk(acc[i][1], o[2], o[3]);
        unpk(acc[i][2], o[4], o[5]); unpk(acc[i][3], o[6], o[7]);
        #pragma unroll
        for (int j = 0; j < 8; j++) {
            float v = o[j] + bvv[j];
            if (ACT == 1) v = gelu_f(v);
            else if (ACT == 2) v = sigmoid_f(v);
            o[j] = v;
        }
        float4 s0 = {o[0], o[1], o[2], o[3]};
        float4 s1 = {o[4], o[5], o[6], o[7]};
        *(float4*)(C + (size_t)(m0 + r) * 256 + n0 + (tc << 2))      = s0;
        *(float4*)(C + (size_t)(m0 + r) * 256 + n0 + 64 + (tc << 2)) = s1;
    }
}

template<int NSRC, int ACT>
__global__ void __launch_bounds__(256, 2) gemm_k(
    const float* __restrict__ A0, const float* __restrict__ A1,
    const float* __restrict__ A2, const float* __restrict__ A3,
    const float* __restrict__ W, const float* __restrict__ bias,
    float* __restrict__ C)
{
    extern __shared__ float gsm[];
    gemm_core<NSRC, ACT>(A0, A1, A2, A3, W, bias, C,
                         blockIdx.x << 7, blockIdx.y << 7, gsm, gsm + 16 * 132);
}

// QKV fused: grid.y = 6 (3 weights x 2 n-blocks)
__global__ void __launch_bounds__(256, 2) gemm_qkv_k(
    const float* __restrict__ A, const float* __restrict__ Wb,
    const float* __restrict__ bb,
    float* __restrict__ Cq, float* __restrict__ Ck, float* __restrict__ Cv)
{
    extern __shared__ float gsm[];
    int s = blockIdx.y >> 1;
    int n0 = (blockIdx.y & 1) << 7;
    float* C = (s == 0) ? Cq : ((s == 1) ? Ck : Cv);
    gemm_core<1, 0>(A, 0, 0, 0, Wb + s * 65536, bb + s * 256, C,
                    blockIdx.x << 7, n0, gsm, gsm + 16 * 132);
}

// gate(sigmoid) + transform(gelu) fused: grid.y = 4
__global__ void __launch_bounds__(256, 2) gemm_gt_k(
    const float* __restrict__ A0, const float* __restrict__ A1,
    const float* __restrict__ A2, const float* __restrict__ A3,
    const float* __restrict__ gw, const float* __restrict__ gb,
    const float* __restrict__ tw, const float* __restrict__ tb,
    float* __restrict__ G, float* __restrict__ U)
{
    extern __shared__ float gsm[];
    int n0 = (blockIdx.y & 1) << 7;
    if (blockIdx.y < 2)
        gemm_core<4, 2>(A0, A1, A2, A3, gw, gb, G, blockIdx.x << 7, n0, gsm, gsm + 16 * 132);
    else
        gemm_core<4, 1>(A0, A1, A2, A3, tw, tb, U, blockIdx.x << 7, n0, gsm, gsm + 16 * 132);
}

// arc head + dep fused: grid.y = 4
__global__ void __launch_bounds__(256, 2) gemm_arc_k(
    const float* __restrict__ A,
    const float* __restrict__ ahw, const float* __restrict__ ahb,
    const float* __restrict__ adw, const float* __restrict__ adb,
    float* __restrict__ Ch, float* __restrict__ Cd)
{
    extern __shared__ float gsm[];
    int s = blockIdx.y >> 1;
    int n0 = (blockIdx.y & 1) << 7;
    gemm_core<1, 0>(A, 0, 0, 0, s ? adw : ahw, s ? adb : ahb, s ? Cd : Ch,
                    blockIdx.x << 7, n0, gsm, gsm + 16 * 132);
}

// ---------------------------------------------------------------------------
// Attention per (b, h), flash-style online softmax, no score buffer.
// 128 threads = 1 per query. smem = K,V (64KB) + ph/mask. 3 blocks/SM.
// MODE 0: K/V rows gathered via pred_heads. MODE 1: sibling block mask.
// ---------------------------------------------------------------------------
#define ATTN_SMEM ((8192 + 8192 + 256) * 4)

template<int MODE>
__global__ void __launch_bounds__(128, 3) attn_k(
    const float* __restrict__ Q, const float* __restrict__ Kp,
    const float* __restrict__ Vp, const int* __restrict__ ph,
    const float* __restrict__ mask, float* __restrict__ O)
{
    extern __shared__ float sm[];
    float* Ks  = sm;                 // [128][64]
    float* Vs  = sm + 8192;          // [128][64]
    int*   phs = (int*)(sm + 16384);
    float* msk = sm + 16384 + 128;

    const int b = blockIdx.x, h = blockIdx.y, t = threadIdx.x;
    const int rowbase = b * NN;

    phs[t] = ph[rowbase + t];
    msk[t] = mask[rowbase + t];
    __syncthreads();

    for (int i = t; i < 2048; i += 128) {      // 128 rows x 16 float4
        int krow = i >> 4;
        int f4   = (i & 15) << 2;
        int src  = (MODE == 0) ? min(max(phs[krow], 0), NN - 1) : krow;
        size_t off = (size_t)(rowbase + src) * DM + h * HDD + f4;
        *(float4*)&Ks[(krow << 6) + f4] = *(const float4*)(Kp + off);
        *(float4*)&Vs[(krow << 6) + f4] = *(const float4*)(Vp + off);
    }
    __syncthreads();

    float q[64];
    {
        size_t off = (size_t)(rowbase + t) * DM + h * HDD;
        #pragma unroll
        for (int d = 0; d < 64; d += 4) {
            float4 v = *(const float4*)(Q + off + d);
            q[d] = v.x; q[d+1] = v.y; q[d+2] = v.z; q[d+3] = v.w;
        }
    }
    const int   myph = (MODE == 1) ? phs[t] : 0;
    const float mym  = (MODE == 1) ? msk[t] : 1.f;

    float m = -3.402823466e38f, l = 0.f;
    float o[64];
    #pragma unroll
    for (int d = 0; d < 64; d++) o[d] = 0.f;

    for (int kc = 0; kc < 128; kc += 8) {
        float s[8];
        #pragma unroll
        for (int j = 0; j < 8; j++) {
            const float4* kr = (const float4*)&Ks[(kc + j) << 6];
            float acc = 0.f;
            #pragma unroll
            for (int d4 = 0; d4 < 16; d4++) {
                float4 kv = kr[d4];
                acc += q[4*d4]*kv.x + q[4*d4+1]*kv.y + q[4*d4+2]*kv.z + q[4*d4+3]*kv.w;
            }
            acc *= 0.125f;  // 1/sqrt(64)
            if (MODE == 1) {
                int k = kc + j;
                bool sib = (phs[k] == myph) && (k != t) && (msk[k] > 0.f) && (mym > 0.f);
                if (!sib) acc = -1e9f;
            }
            s[j] = acc;
        }
        float cm = s[0];
        #pragma unroll
        for (int j = 1; j < 8; j++) cm = fmaxf(cm, s[j]);
        if (cm > m) {
            float corr = expf(m - cm);
            l *= corr;
            #pragma unroll
            for (int d = 0; d < 64; d++) o[d] *= corr;
            m = cm;
        }
        #pragma unroll
        for (int j = 0; j < 8; j++) {
            float p = expf(s[j] - m);
            l += p;
            const float4* vr = (const float4*)&Vs[(kc + j) << 6];
            #pragma unroll
            for (int d4 = 0; d4 < 16; d4++) {
                float4 vv = vr[d4];
                o[4*d4]   += p*vv.x; o[4*d4+1] += p*vv.y;
                o[4*d4+2] += p*vv.z; o[4*d4+3] += p*vv.w;
            }
        }
    }
    float inv = 1.f / l;
    size_t off = (size_t)(rowbase + t) * DM + h * HDD;
    #pragma unroll
    for (int d = 0; d < 64; d += 4) {
        float4 v = {o[d]*inv, o[d+1]*inv, o[d+2]*inv, o[d+3]*inv};
        *(float4*)(O + off + d) = v;
    }
}

// ---------------------------------------------------------------------------
// Child scatter-mean, atomic-free: block per (b, dim-half). 128 threads each
// own one dim; smem [128 heads][128 dims] accumulator, thread-private columns.
// ---------------------------------------------------------------------------
#define CHILD_SMEM (128 * 128 * 4)

__global__ void __launch_bounds__(128) child_k(
    const float* __restrict__ Hr, const int* __restrict__ ph,
    const float* __restrict__ mask, float* __restrict__ out)
{
    extern __shared__ float sm[];
    __shared__ int   phs[128];
    __shared__ float msk[128], inv[128];
    const int b = blockIdx.x, t = threadIdx.x;
    const int d0 = blockIdx.y << 7;

    phs[t] = min(max(ph[b * 128 + t], 0), 127);
    msk[t] = mask[b * 128 + t];
    for (int i = t; i < 16384; i += 128) sm[i] = 0.f;
    __syncthreads();

    float c = 0.f;
    #pragma unroll 4
    for (int n = 0; n < 128; n++) c += (phs[n] == t) ? msk[n] : 0.f;
    inv[t] = 1.f / fmaxf(c, 1.f);

    #pragma unroll 4
    for (int n = 0; n < 128; n++) {
        int hrow = phs[n];
        sm[(hrow << 7) + t] += Hr[(size_t)(b * 128 + n) * 256 + d0 + t];
    }
    __syncthreads();

    for (int hh = 0; hh < 128; hh++)
        out[(size_t)(b * 128 + hh) * 256 + d0 + t] = sm[(hh << 7) + t] * inv[hh];
}

// ---------------------------------------------------------------------------
// Fused gate*update + residual + LayerNorm (one block per row, 256 threads)
// ---------------------------------------------------------------------------
__global__ void __launch_bounds__(256) fuse_ln_k(
    float* __restrict__ Hr, const float* __restrict__ g, const float* __restrict__ u,
    const float* __restrict__ lg, const float* __restrict__ lb)
{
    __shared__ float shs[8], shq[8];
    __shared__ float stat[2];
    int row = blockIdx.x, t = threadIdx.x;
    size_t off = (size_t)row * 256 + t;
    float x = Hr[off] + g[off] * u[off];
    float s = x, qq = x * x;
    #pragma unroll
    for (int o = 16; o; o >>= 1) {
        s  += __shfl_xor_sync(0xffffffffu, s, o);
        qq += __shfl_xor_sync(0xffffffffu, qq, o);
    }
    if ((t & 31) == 0) { shs[t >> 5] = s; shq[t >> 5] = qq; }
    __syncthreads();
    if (t == 0) {
        float S = 0.f, Q = 0.f;
        #pragma unroll
        for (int i = 0; i < 8; i++) { S += shs[i]; Q += shq[i]; }
        float mu = S * (1.f / 256.f);
        float var = fmaxf(Q * (1.f / 256.f) - mu * mu, 0.f);
        stat[0] = mu;
        stat[1] = rsqrtf(var + 1e-5f);
    }
    __syncthreads();
    Hr[off] = (x - stat[0]) * stat[1] * lg[t] + lb[t];
}

// ---------------------------------------------------------------------------
// bias vector: out[row] = dot(X[row,:], w) + b0   (warp per row)
// ---------------------------------------------------------------------------
__global__ void __launch_bounds__(256) biasvec_k(
    const float* __restrict__ X, const float* __restrict__ w,
    const float* __restrict__ b0, float* __restrict__ out)
{
    int row  = blockIdx.x * 8 + (threadIdx.x >> 5);
    int lane = threadIdx.x & 31;
    const float* x = X + (size_t)row * 256;
    float s = 0.f;
    for (int d = lane; d < 256; d += 32) s += x[d] * w[d];
    #pragma unroll
    for (int o = 16; o; o >>= 1) s += __shfl_xor_sync(0xffffffffu, s, o);
    if (lane == 0) out[row] = s + b0[0];
}

// ---------------------------------------------------------------------------
// Final scores: one block per b: S[b,n,m] = T[b,n,:].Hd[b,m,:] + bd[n] + bh[m]
// 128x128 tile, 256 threads, 8x8 micro with f32x2.
// ---------------------------------------------------------------------------
#define SSM_BYTES ((16*132 * 2) * 4)

__global__ void __launch_bounds__(256, 2) scores2_k(
    const float* __restrict__ T, const float* __restrict__ Hd,
    const float* __restrict__ bh, const float* __restrict__ bd,
    float* __restrict__ S)
{
    extern __shared__ float smx[];
    float* As = smx;
    float* Bs = smx + 16 * 132;
    const int b = blockIdx.x;
    const int tid = threadIdx.x;
    const int tr = tid >> 4, tc = tid & 15;
    const int ra = tid >> 2, ca = (tid & 3) << 2;
    const float* Ab = T  + (size_t)b * NN * DM;
    const float* Bb = Hd + (size_t)b * NN * DM;

    unsigned long long acc[8][4];
    #pragma unroll
    for (int i = 0; i < 8; i++)
        #pragma unroll
        for (int j = 0; j < 4; j++) acc[i][j] = 0ull;

    float4 a0, a1, b0, b1;
    a0 = *(const float4*)(Ab + (size_t)ra * 256 + ca);
    a1 = *(const float4*)(Ab + (size_t)(ra + 64) * 256 + ca);
    b0 = *(const float4*)(Bb + (size_t)ra * 256 + ca);
    b1 = *(const float4*)(Bb + (size_t)(ra + 64) * 256 + ca);

    for (int kt = 0; kt < 256; kt += 16) {
        __syncthreads();
        As[(ca+0)*132 + ra] = a0.x; As[(ca+1)*132 + ra] = a0.y;
        As[(ca+2)*132 + ra] = a0.z; As[(ca+3)*132 + ra] = a0.w;
        As[(ca+0)*132 + ra + 64] = a1.x; As[(ca+1)*132 + ra + 64] = a1.y;
        As[(ca+2)*132 + ra + 64] = a1.z; As[(ca+3)*132 + ra + 64] = a1.w;
        Bs[(ca+0)*132 + ra] = b0.x; Bs[(ca+1)*132 + ra] = b0.y;
        Bs[(ca+2)*132 + ra] = b0.z; Bs[(ca+3)*132 + ra] = b0.w;
        Bs[(ca+0)*132 + ra + 64] = b1.x; Bs[(ca+1)*132 + ra + 64] = b1.y;
        Bs[(ca+2)*132 + ra + 64] = b1.z; Bs[(ca+3)*132 + ra + 64] = b1.w;
        __syncthreads();
        if (kt + 16 < 256) {
            a0 = *(const float4*)(Ab + (size_t)ra * 256 + kt + 16 + ca);
            a1 = *(const float4*)(Ab + (size_t)(ra + 64) * 256 + kt + 16 + ca);
            b0 = *(const float4*)(Bb + (size_t)ra * 256 + kt + 16 + ca);
            b1 = *(const float4*)(Bb + (size_t)(ra + 64) * 256 + kt + 16 + ca);
        }
        #pragma unroll
        for (int kk = 0; kk < 16; kk++) {
            float4 av0 = *(const float4*)&As[kk*132 + (tr << 2)];
            float4 av1 = *(const float4*)&As[kk*132 + 64 + (tr << 2)];
            ulonglong2 bq0 = *(const ulonglong2*)&Bs[kk*132 + (tc << 2)];
            ulonglong2 bq1 = *(const ulonglong2*)&Bs[kk*132 + 64 + (tc << 2)];
            float a_[8] = {av0.x, av0.y, av0.z, av0.w, av1.x, av1.y, av1.z, av1.w};
            #pragma unroll
            for (int i = 0; i < 8; i++) {
                unsigned long long ap;
                asm("mov.b64 %0, {%1, %1};" : "=l"(ap) : "f"(a_[i]));
                asm("fma.rn.f32x2 %0, %1, %2, %0;" : "+l"(acc[i][0]) : "l"(ap), "l"(bq0.x));
                asm("fma.rn.f32x2 %0, %1, %2, %0;" : "+l"(acc[i][1]) : "l"(ap), "l"(bq0.y));
                asm("fma.rn.f32x2 %0, %1, %2, %0;" : "+l"(acc[i][2]) : "l"(ap), "l"(bq1.x));
                asm("fma.rn.f32x2 %0, %1, %2, %0;" : "+l"(acc[i][3]) : "l"(ap), "l"(bq1.y));
            }
        }
    }

    float cb[8];
    #pragma unroll
    for (int j = 0; j < 8; j++) {
        int c = (j < 4) ? ((tc << 2) + j) : (64 + (tc << 2) + j - 4);
        cb[j] = bh[b * NN + c];
    }
    #pragma unroll
    for (int i = 0; i < 8; i++) {
        int n = (i < 4) ? ((tr << 2) + i) : (64 + (tr << 2) + i - 4);
        float rb = bd[b * NN + n];
        float o[8];
        unpk(acc[i][0], o[0], o[1]); unpk(acc[i][1], o[2], o[3]);
        unpk(acc[i][2], o[4], o[5]); unpk(acc[i][3], o[6], o[7]);
        float4 s0 = {o[0]+rb+cb[0], o[1]+rb+cb[1], o[2]+rb+cb[2], o[3]+rb+cb[3]};
        float4 s1 = {o[4]+rb+cb[4], o[5]+rb+cb[5], o[6]+rb+cb[6], o[7]+rb+cb[7]};
        *(float4*)(S + (size_t)b * NN * NN + (size_t)n * NN + (tc << 2))      = s0;
        *(float4*)(S + (size_t)b * NN * NN + (size_t)n * NN + 64 + (tc << 2)) = s1;
    }
}

// ---------------------------------------------------------------------------
// Host orchestration
// ---------------------------------------------------------------------------
extern "C" void kernel_launch(void* const* d_in, const int* in_sizes, int n_in,
                              void* d_out, int out_size)
{
    const float* Hin    = (const float*)d_in[0];
    const int*   ph     = (const int*)  d_in[1];
    const float* mask   = (const float*)d_in[2];
    const float* ha_w   = (const float*)d_in[3];
    const float* ha_b   = (const float*)d_in[4];
    const float* sa_w   = (const float*)d_in[5];
    const float* sa_b   = (const float*)d_in[6];
    const float* ct_w   = (const float*)d_in[7];
    const float* ct_b   = (const float*)d_in[8];
    const float* gate_w = (const float*)d_in[9];
    const float* gate_b = (const float*)d_in[10];
    const float* tr_w   = (const float*)d_in[11];
    const float* tr_b   = (const float*)d_in[12];
    const float* ln_g   = (const float*)d_in[13];
    const float* ln_b   = (const float*)d_in[14];
    const float* ahw    = (const float*)d_in[15];
    const float* ahb    = (const float*)d_in[16];
    const float* adw    = (const float*)d_in[17];
    const float* adb    = (const float*)d_in[18];
    const float* bil    = (const float*)d_in[19];
    const float* bhw    = (const float*)d_in[20];
    const float* bhb    = (const float*)d_in[21];
    const float* bdw    = (const float*)d_in[22];
    const float* bdb    = (const float*)d_in[23];

    float* Hr     = (float*)d_out;                 // [B,N,Dm]
    float* scores = Hr + (size_t)MR * DM;          // [B,N,N]

    float *q_, *k_, *v_, *at_, *hm_, *cav_, *cm_, *sb_, *ga_, *tu_, *bhv_, *bdv_;
    cudaGetSymbolAddress((void**)&q_,   g_q);
    cudaGetSymbolAddress((void**)&k_,   g_k);
    cudaGetSymbolAddress((void**)&v_,   g_v);
    cudaGetSymbolAddress((void**)&at_,  g_attn);
    cudaGetSymbolAddress((void**)&hm_,  g_head);
    cudaGetSymbolAddress((void**)&cav_, g_childavg);
    cudaGetSymbolAddress((void**)&cm_,  g_childmsg);
    cudaGetSymbolAddress((void**)&sb_,  g_sib);
    cudaGetSymbolAddress((void**)&ga_,  g_gate);
    cudaGetSymbolAddress((void**)&tu_,  g_tr);
    cudaGetSymbolAddress((void**)&bhv_, g_bh);
    cudaGetSymbolAddress((void**)&bdv_, g_bd);

    cudaFuncSetAttribute(attn_k<0>, cudaFuncAttributeMaxDynamicSharedMemorySize, ATTN_SMEM);
    cudaFuncSetAttribute(attn_k<1>, cudaFuncAttributeMaxDynamicSharedMemorySize, ATTN_SMEM);
    cudaFuncSetAttribute(child_k,   cudaFuncAttributeMaxDynamicSharedMemorySize, CHILD_SMEM);

    cudaMemcpyAsync(Hr, Hin, sizeof(float) * (size_t)MR * DM, cudaMemcpyDeviceToDevice);

    dim3 gb(256);
    dim3 ag(BB, NHH);

    for (int i = 0; i < 3; i++) {
        const float* hw = ha_w + (size_t)i * 4 * DM * DM;
        const float* hb = ha_b + (size_t)i * 4 * DM;
        // head attention: proj(gather(Hr)) == gather(proj(Hr))
        gemm_qkv_k<<<dim3(256, 6), gb, GSM_BYTES>>>(Hr, hw, hb, q_, k_, v_);
        attn_k<0><<<ag, 128, ATTN_SMEM>>>(q_, k_, v_, ph, mask, at_);
        gemm_k<1,0><<<dim3(256, 2), gb, GSM_BYTES>>>(at_, 0, 0, 0, hw + 3*65536, hb + 768, hm_);

        // child scatter-mean (atomic-free) + gelu MLP on concat(Hr, child_avg)
        child_k<<<dim3(256, 2), 128, CHILD_SMEM>>>(Hr, ph, mask, cav_);
        gemm_k<2,1><<<dim3(256, 2), gb, GSM_BYTES>>>(Hr, cav_, 0, 0,
                                ct_w + (size_t)i * 512 * 256, ct_b + i * 256, cm_);

        // sibling masked self-attention
        const float* sw = sa_w + (size_t)i * 4 * DM * DM;
        const float* sbb = sa_b + (size_t)i * 4 * DM;
        gemm_qkv_k<<<dim3(256, 6), gb, GSM_BYTES>>>(Hr, sw, sbb, q_, k_, v_);
        attn_k<1><<<ag, 128, ATTN_SMEM>>>(q_, k_, v_, ph, mask, at_);
        gemm_k<1,0><<<dim3(256, 2), gb, GSM_BYTES>>>(at_, 0, 0, 0, sw + 3*65536, sbb + 768, sb_);

        // gated fuse + residual + LN
        gemm_gt_k<<<dim3(256, 4), gb, GSM_BYTES>>>(Hr, hm_, cm_, sb_,
                                gate_w + (size_t)i * 1024 * 256, gate_b + i * 256,
                                tr_w   + (size_t)i * 1024 * 256, tr_b   + i * 256,
                                ga_, tu_);
        fuse_ln_k<<<MR, 256>>>(Hr, ga_, tu_, ln_g + i * 256, ln_b + i * 256);
    }

    // final biaffine scorer
    gemm_arc_k<<<dim3(256, 4), gb, GSM_BYTES>>>(Hr, ahw, ahb, adw, adb, q_, k_);
    gemm_k<1,0><<<dim3(256, 2), gb, GSM_BYTES>>>(q_, 0, 0, 0, bil, nullptr, v_);  // T = h_head @ bilinear
    biasvec_k<<<MR / 8, 256>>>(q_, bhw, bhb, bhv_);
    biasvec_k<<<MR / 8, 256>>>(k_, bdw, bdb, bdv_);
    scores2_k<<<BB, 256, SSM_BYTES>>>(v_, k_, bhv_, bdv_, scores);
}